// round 14
// baseline (speedup 1.0000x reference)
#include <cuda_runtime.h>

// ---------------------------------------------------------------------------
// Problem constants
// ---------------------------------------------------------------------------
#define N_PFAS 50000
#define N_GW   200000
#define N_SW   20000
#define D      32
#define E_PG   2000000
#define E_GP   2000000
#define E_PS   1000000
#define E_SP   1000000

#define OFF_Y   (N_PFAS * D)
#define OFF_SW  (N_PFAS * D + N_GW)

#define NB_PF  ((N_PFAS + 255) / 256)   // 196
#define NB_SW  ((N_SW + 255) / 256)     // 79
#define GW_GRID 296                     // ~2 blocks/SM: caps fin_gw footprint

typedef unsigned long long u64;

// ---------------------------------------------------------------------------
// Scratch (device globals; allocation-free). 16B aligned for v4 atomics/loads.
// ---------------------------------------------------------------------------
__device__ __align__(16) float g_sum_pg[(size_t)N_GW * D];
__device__ __align__(16) float g_cnt_pg[N_GW];
__device__ __align__(16) int   g_maxe_pg[N_GW];

__device__ __align__(16) float g_sum_gp[(size_t)N_PFAS * D];
__device__ __align__(16) float g_cnt_gp[N_PFAS];
__device__ __align__(16) int   g_maxe_gp[N_PFAS];

__device__ __align__(16) float g_sum_sp[(size_t)N_PFAS * D];
__device__ __align__(16) float g_cnt_sp[N_PFAS];

__device__ __align__(16) float g_sum_ps[(size_t)N_SW * D];
__device__ __align__(16) float g_cnt_ps[N_SW];

// ---------------------------------------------------------------------------
// Static stream/events for the capture-graph fork.
// ---------------------------------------------------------------------------
struct OverlapRes {
    cudaStream_t s;
    cudaEvent_t  eFork, e0, e1, e2, e3, eInit;
    OverlapRes() {
        cudaStreamCreateWithFlags(&s, cudaStreamNonBlocking);
        cudaEventCreateWithFlags(&eFork, cudaEventDisableTiming);
        cudaEventCreateWithFlags(&e0, cudaEventDisableTiming);
        cudaEventCreateWithFlags(&e1, cudaEventDisableTiming);
        cudaEventCreateWithFlags(&e2, cudaEventDisableTiming);
        cudaEventCreateWithFlags(&e3, cudaEventDisableTiming);
        cudaEventCreateWithFlags(&eInit, cudaEventDisableTiming);
    }
};
static OverlapRes g_res;

// ---------------------------------------------------------------------------
// Packed f32x2 helpers (sm_100+)
// ---------------------------------------------------------------------------
__device__ __forceinline__ u64 pk2(float x) {
    u64 d; unsigned xi = __float_as_uint(x);
    asm("mov.b64 %0, {%1, %1};" : "=l"(d) : "r"(xi));
    return d;
}
__device__ __forceinline__ u64 pk2f(float a, float b) {
    u64 d; unsigned ai = __float_as_uint(a), bi = __float_as_uint(b);
    asm("mov.b64 %0, {%1, %2};" : "=l"(d) : "r"(ai), "r"(bi));
    return d;
}
__device__ __forceinline__ u64 f2fma(u64 a, u64 b, u64 c) {
    u64 d; asm("fma.rn.f32x2 %0, %1, %2, %3;" : "=l"(d) : "l"(a), "l"(b), "l"(c));
    return d;
}
__device__ __forceinline__ u64 f2add(u64 a, u64 b) {
    u64 d; asm("add.rn.f32x2 %0, %1, %2;" : "=l"(d) : "l"(a), "l"(b));
    return d;
}
__device__ __forceinline__ float2 up2(u64 a) {
    unsigned lo, hi;
    asm("mov.b64 {%0, %1}, %2;" : "=r"(lo), "=r"(hi) : "l"(a));
    return make_float2(__uint_as_float(lo), __uint_as_float(hi));
}

__device__ __forceinline__ void red_add_v4(float* addr, float4 v) {
    asm volatile("red.global.add.v4.f32 [%0], {%1,%2,%3,%4};"
                 :: "l"(addr), "f"(v.x), "f"(v.y), "f"(v.z), "f"(v.w)
                 : "memory");
}

// ---------------------------------------------------------------------------
// Init split: pg-only (crit path) and the rest (hidden under agg_pg).
// Vectorized float4/int4 stores.
// ---------------------------------------------------------------------------
__global__ void k_init_pg() {
    int i = blockIdx.x * blockDim.x + threadIdx.x;
    int stride = gridDim.x * blockDim.x;
    float4 z4 = make_float4(0.f, 0.f, 0.f, 0.f);
    int4 m4 = make_int4(-1, -1, -1, -1);
    float4* s = (float4*)g_sum_pg;
    for (int j = i; j < N_GW * D / 4; j += stride) s[j] = z4;
    float4* c = (float4*)g_cnt_pg;
    for (int j = i; j < N_GW / 4; j += stride) c[j] = z4;
    int4* m = (int4*)g_maxe_pg;
    for (int j = i; j < N_GW / 4; j += stride) m[j] = m4;
}

__global__ void k_init_rest() {
    int i = blockIdx.x * blockDim.x + threadIdx.x;
    int stride = gridDim.x * blockDim.x;
    float4 z4 = make_float4(0.f, 0.f, 0.f, 0.f);
    int4 m4 = make_int4(-1, -1, -1, -1);
    float4* sg = (float4*)g_sum_gp;
    float4* ss = (float4*)g_sum_sp;
    for (int j = i; j < N_PFAS * D / 4; j += stride) { sg[j] = z4; ss[j] = z4; }
    float4* sp = (float4*)g_sum_ps;
    for (int j = i; j < N_SW * D / 4; j += stride) sp[j] = z4;
    float4* cg = (float4*)g_cnt_gp;
    float4* cs = (float4*)g_cnt_sp;
    int4* mg = (int4*)g_maxe_gp;
    for (int j = i; j < N_PFAS / 4; j += stride) { cg[j] = z4; cs[j] = z4; mg[j] = m4; }
    float4* cp = (float4*)g_cnt_ps;
    for (int j = i; j < N_SW / 4; j += stride) cp[j] = z4;
}

// ---------------------------------------------------------------------------
// Single-relation edge aggregation (8-lane groups, 4 edges/group)
// ---------------------------------------------------------------------------
__global__ void k_agg_rel(const float4* __restrict__ X,
                          const int4*   __restrict__ src4,
                          const int4*   __restrict__ dst4,
                          float* __restrict__ sum,
                          float* __restrict__ cnt,
                          int*   __restrict__ maxe,
                          int ngroups)
{
    int t   = blockIdx.x * blockDim.x + threadIdx.x;
    int g   = t >> 3;
    int seg = t & 7;
    if (g >= ngroups) return;

    int4 s4 = __ldg(&src4[g]);
    int4 d4 = __ldg(&dst4[g]);

    float4 v0 = __ldg(&X[(size_t)s4.x * 8 + seg]);
    float4 v1 = __ldg(&X[(size_t)s4.y * 8 + seg]);
    float4 v2 = __ldg(&X[(size_t)s4.z * 8 + seg]);
    float4 v3 = __ldg(&X[(size_t)s4.w * 8 + seg]);

    red_add_v4(&sum[(size_t)d4.x * D + seg * 4], v0);
    red_add_v4(&sum[(size_t)d4.y * D + seg * 4], v1);
    red_add_v4(&sum[(size_t)d4.z * D + seg * 4], v2);
    red_add_v4(&sum[(size_t)d4.w * D + seg * 4], v3);

    if (seg == 0) {
        atomicAdd(&cnt[d4.x], 1.0f);
        atomicAdd(&cnt[d4.y], 1.0f);
        atomicAdd(&cnt[d4.z], 1.0f);
        atomicAdd(&cnt[d4.w], 1.0f);
        if (maxe) {
            int e0 = g * 4;
            atomicMax(&maxe[d4.x], e0);
            atomicMax(&maxe[d4.y], e0 + 1);
            atomicMax(&maxe[d4.z], e0 + 2);
            atomicMax(&maxe[d4.w], e0 + 3);
        }
    }
}

// ---------------------------------------------------------------------------
// Thread-per-node epilogues
// ---------------------------------------------------------------------------
__device__ __forceinline__ void load_row(const float* base, size_t n, float inv, float x[32]) {
    const float4* r4 = (const float4*)(base + n * D);
#pragma unroll
    for (int q = 0; q < 8; q++) {
        float4 v = __ldg(&r4[q]);
        x[q * 4 + 0] = v.x * inv; x[q * 4 + 1] = v.y * inv;
        x[q * 4 + 2] = v.z * inv; x[q * 4 + 3] = v.w * inv;
    }
}

__device__ __forceinline__ void mv_acc(const float* sW, const float x[32], u64 acc[16]) {
#pragma unroll
    for (int k = 0; k < 32; k++) {
        u64 xk = pk2(x[k]);
        const u64* w2 = (const u64*)(sW + k * 32);
#pragma unroll
        for (int jj = 0; jj < 16; jj++) acc[jj] = f2fma(xk, w2[jj], acc[jj]);
    }
}

__device__ __forceinline__ void edge_acc(const float* __restrict__ ea, int me,
                                         const float* sWe, const float* sbe,
                                         u64 acc[16]) {
    u64 e0 = pk2(__ldg(&ea[3 * (size_t)me + 0]));
    u64 e1 = pk2(__ldg(&ea[3 * (size_t)me + 1]));
    u64 e2 = pk2(__ldg(&ea[3 * (size_t)me + 2]));
    const u64* w0 = (const u64*)(sWe);
    const u64* w1 = (const u64*)(sWe + 32);
    const u64* w2 = (const u64*)(sWe + 64);
#pragma unroll
    for (int jj = 0; jj < 16; jj++) {
        u64 a = acc[jj];
        a = f2fma(e0, w0[jj], a);
        a = f2fma(e1, w1[jj], a);
        a = f2fma(e2, w2[jj], a);
        a = f2add(a, pk2f(sbe[2 * jj], sbe[2 * jj + 1]));
        acc[jj] = a;
    }
}

// GW epilogue: grid-stride, footprint-capped at GW_GRID blocks.
__global__ void __launch_bounds__(256) k_fin_gw(
        const float* __restrict__ x_gw, const float* __restrict__ ea,
        const float* __restrict__ Wl, const float* __restrict__ bl,
        const float* __restrict__ Wr, const float* __restrict__ We,
        const float* __restrict__ be, const float* __restrict__ Wo,
        const float* __restrict__ bout, const float* __restrict__ apre,
        float* __restrict__ y)
{
    __shared__ __align__(16) float sW[2 * 1024];
    __shared__ __align__(16) float sWe[96];
    __shared__ float sb[32], sbe[32], sWo[32];
    int tid = threadIdx.x;
    for (int j = tid; j < 1024; j += 256) { sW[j] = Wl[j]; sW[1024 + j] = Wr[j]; }
    if (tid < 96) sWe[tid] = We[tid];
    if (tid < 32) { sb[tid] = bl[tid]; sbe[tid] = be[tid]; sWo[tid] = Wo[tid]; }
    __syncthreads();

    float bo = __ldg(&bout[0]);
    float a_ = __ldg(&apre[0]);

    for (int n0 = blockIdx.x * 256; n0 < N_GW; n0 += gridDim.x * 256) {
        int n = n0 + tid;
        if (n >= N_GW) continue;

        u64 acc[16];
#pragma unroll
        for (int jj = 0; jj < 16; jj++) acc[jj] = pk2f(sb[2 * jj], sb[2 * jj + 1]);

        float inv = 1.0f / fmaxf(g_cnt_pg[n], 1.0f);
        float xr[32];
        load_row(g_sum_pg, (size_t)n, inv, xr);
        mv_acc(sW, xr, acc);
        load_row(x_gw, (size_t)n, 1.0f, xr);
        mv_acc(sW + 1024, xr, acc);

        int me = g_maxe_pg[n];
        if (me >= 0) edge_acc(ea, me, sWe, sbe, acc);

        float yv = 0.0f;
#pragma unroll
        for (int jj = 0; jj < 16; jj++) {
            float2 h = up2(acc[jj]);
            yv += fmaxf(h.x, 0.0f) * sWo[2 * jj] + fmaxf(h.y, 0.0f) * sWo[2 * jj + 1];
        }
        yv += bo;
        y[n] = (yv >= 0.0f) ? yv : a_ * yv;
    }
}

__global__ void __launch_bounds__(256) k_fin_pfas(
        const float* __restrict__ x_pfas, const float* __restrict__ ea,
        const float* __restrict__ Wl_gp, const float* __restrict__ bl_gp,
        const float* __restrict__ Wr_gp, const float* __restrict__ We_gp,
        const float* __restrict__ be_gp,
        const float* __restrict__ Wl_sp, const float* __restrict__ bl_sp,
        const float* __restrict__ Wr_sp,
        float* __restrict__ h_out)
{
    __shared__ __align__(16) float sW[3 * 1024];
    __shared__ __align__(16) float sWe[96];
    __shared__ float sb[32], sbe[32];
    int tid = threadIdx.x;
    for (int j = tid; j < 1024; j += 256) {
        sW[j]        = Wl_gp[j];
        sW[1024 + j] = Wl_sp[j];
        sW[2048 + j] = Wr_gp[j] + Wr_sp[j];
    }
    if (tid < 96) sWe[tid] = We_gp[tid];
    if (tid < 32) { sb[tid] = bl_gp[tid] + bl_sp[tid]; sbe[tid] = be_gp[tid]; }
    __syncthreads();

    int n = blockIdx.x * 256 + tid;
    if (n >= N_PFAS) return;

    u64 acc[16];
#pragma unroll
    for (int jj = 0; jj < 16; jj++) acc[jj] = pk2f(sb[2 * jj], sb[2 * jj + 1]);

    float invg = 1.0f / fmaxf(g_cnt_gp[n], 1.0f);
    float invs = 1.0f / fmaxf(g_cnt_sp[n], 1.0f);
    float xr[32];
    load_row(g_sum_gp, (size_t)n, invg, xr);
    mv_acc(sW, xr, acc);
    load_row(g_sum_sp, (size_t)n, invs, xr);
    mv_acc(sW + 1024, xr, acc);
    load_row(x_pfas, (size_t)n, 1.0f, xr);
    mv_acc(sW + 2048, xr, acc);

    int me = g_maxe_gp[n];
    if (me >= 0) edge_acc(ea, me, sWe, sbe, acc);

    float4* o4 = (float4*)(h_out + (size_t)n * D);
#pragma unroll
    for (int q = 0; q < 8; q++) {
        float2 a = up2(acc[2 * q]);
        float2 c = up2(acc[2 * q + 1]);
        o4[q] = make_float4(fmaxf(a.x, 0.f), fmaxf(a.y, 0.f),
                            fmaxf(c.x, 0.f), fmaxf(c.y, 0.f));
    }
}

__global__ void __launch_bounds__(256) k_fin_sw(
        const float* __restrict__ x_sw,
        const float* __restrict__ Wl, const float* __restrict__ bl,
        const float* __restrict__ Wr,
        float* __restrict__ h_out)
{
    __shared__ __align__(16) float sW[2 * 1024];
    __shared__ float sb[32];
    int tid = threadIdx.x;
    for (int j = tid; j < 1024; j += 256) { sW[j] = Wl[j]; sW[1024 + j] = Wr[j]; }
    if (tid < 32) sb[tid] = bl[tid];
    __syncthreads();

    int n = blockIdx.x * 256 + tid;
    if (n >= N_SW) return;

    u64 acc[16];
#pragma unroll
    for (int jj = 0; jj < 16; jj++) acc[jj] = pk2f(sb[2 * jj], sb[2 * jj + 1]);

    float inv = 1.0f / fmaxf(g_cnt_ps[n], 1.0f);
    float xr[32];
    load_row(g_sum_ps, (size_t)n, inv, xr);
    mv_acc(sW, xr, acc);
    load_row(x_sw, (size_t)n, 1.0f, xr);
    mv_acc(sW + 1024, xr, acc);

    float4* o4 = (float4*)(h_out + (size_t)n * D);
#pragma unroll
    for (int q = 0; q < 8; q++) {
        float2 a = up2(acc[2 * q]);
        float2 c = up2(acc[2 * q + 1]);
        o4[q] = make_float4(fmaxf(a.x, 0.f), fmaxf(a.y, 0.f),
                            fmaxf(c.x, 0.f), fmaxf(c.y, 0.f));
    }
}

// ---------------------------------------------------------------------------
// Launch: forked schedule with split init (legal fork: side stream first
// WAITS on an origin-recorded event before launching work).
//   main : [eFork] -> init_pg -> agg_pg -> [E0] -> wait(eInit) -> agg_gp
//          -> agg_sp -> [E1] -> agg_ps -> [E2] -> wait(E3)
//   side : wait(eFork) -> init_rest -> [eInit] -> wait(E0) -> fin_gw
//          -> wait(E1) -> fin_pfas -> wait(E2) -> fin_sw -> [E3]
// ---------------------------------------------------------------------------
extern "C" void kernel_launch(void* const* d_in, const int* in_sizes, int n_in,
                              void* d_out, int out_size)
{
    const float* x_pfas = (const float*)d_in[0];
    const float* x_gw   = (const float*)d_in[1];
    const float* x_sw   = (const float*)d_in[2];
    const int*   src_pg = (const int*)d_in[3];
    const int*   dst_pg = (const int*)d_in[4];
    const float* ea_pg  = (const float*)d_in[5];
    const int*   src_gp = (const int*)d_in[6];
    const int*   dst_gp = (const int*)d_in[7];
    const float* ea_gp  = (const float*)d_in[8];
    const int*   src_ps = (const int*)d_in[9];
    const int*   dst_ps = (const int*)d_in[10];
    const int*   src_sp = (const int*)d_in[11];
    const int*   dst_sp = (const int*)d_in[12];
    const float* Wl_pg  = (const float*)d_in[13];
    const float* bl_pg  = (const float*)d_in[14];
    const float* Wr_pg  = (const float*)d_in[15];
    const float* We_pg  = (const float*)d_in[16];
    const float* be_pg  = (const float*)d_in[17];
    const float* Wl_gp  = (const float*)d_in[18];
    const float* bl_gp  = (const float*)d_in[19];
    const float* Wr_gp  = (const float*)d_in[20];
    const float* We_gp  = (const float*)d_in[21];
    const float* be_gp  = (const float*)d_in[22];
    const float* Wl_ps  = (const float*)d_in[23];
    const float* bl_ps  = (const float*)d_in[24];
    const float* Wr_ps  = (const float*)d_in[25];
    const float* Wl_sp  = (const float*)d_in[26];
    const float* bl_sp  = (const float*)d_in[27];
    const float* Wr_sp  = (const float*)d_in[28];
    const float* W_out  = (const float*)d_in[29];
    const float* b_out  = (const float*)d_in[30];
    const float* a_pre  = (const float*)d_in[31];

    float* out      = (float*)d_out;
    float* out_pfas = out;
    float* out_y    = out + OFF_Y;
    float* out_sw   = out + OFF_SW;

    float *p_sum_pg, *p_cnt_pg, *p_sum_gp, *p_cnt_gp, *p_sum_sp, *p_cnt_sp, *p_sum_ps, *p_cnt_ps;
    int *p_maxe_pg, *p_maxe_gp;
    cudaGetSymbolAddress((void**)&p_sum_pg, g_sum_pg);
    cudaGetSymbolAddress((void**)&p_cnt_pg, g_cnt_pg);
    cudaGetSymbolAddress((void**)&p_sum_gp, g_sum_gp);
    cudaGetSymbolAddress((void**)&p_cnt_gp, g_cnt_gp);
    cudaGetSymbolAddress((void**)&p_sum_sp, g_sum_sp);
    cudaGetSymbolAddress((void**)&p_cnt_sp, g_cnt_sp);
    cudaGetSymbolAddress((void**)&p_sum_ps, g_sum_ps);
    cudaGetSymbolAddress((void**)&p_cnt_ps, g_cnt_ps);
    cudaGetSymbolAddress((void**)&p_maxe_pg, g_maxe_pg);
    cudaGetSymbolAddress((void**)&p_maxe_gp, g_maxe_gp);

    cudaStream_t S = g_res.s;

    // --- fork: origin records eFork; side stream joins capture by waiting ---
    cudaEventRecord(g_res.eFork, 0);
    cudaStreamWaitEvent(S, g_res.eFork, 0);

    // --- side stream: zero non-pg scratch (hidden under init_pg + agg_pg) ---
    k_init_rest<<<512, 256, 0, S>>>();
    cudaEventRecord(g_res.eInit, S);

    // --- main stream: pg init + pg aggregation ---
    k_init_pg<<<1024, 256>>>();
    {
        int ng = E_PG / 4;
        k_agg_rel<<<(ng * 8 + 255) / 256, 256>>>(
            (const float4*)x_pfas, (const int4*)src_pg, (const int4*)dst_pg,
            p_sum_pg, p_cnt_pg, p_maxe_pg, ng);
    }
    cudaEventRecord(g_res.e0, 0);

    // --- side stream: GW epilogue (footprint-capped) overlaps remaining aggs ---
    cudaStreamWaitEvent(S, g_res.e0, 0);
    k_fin_gw<<<GW_GRID, 256, 0, S>>>(x_gw, ea_pg,
                                     Wl_pg, bl_pg, Wr_pg, We_pg, be_pg,
                                     W_out, b_out, a_pre, out_y);

    // --- main stream: gp + sp aggregations (after init_rest) ---
    cudaStreamWaitEvent(0, g_res.eInit, 0);
    {
        int ng = E_GP / 4;
        k_agg_rel<<<(ng * 8 + 255) / 256, 256>>>(
            (const float4*)x_gw, (const int4*)src_gp, (const int4*)dst_gp,
            p_sum_gp, p_cnt_gp, p_maxe_gp, ng);
    }
    {
        int ng = E_SP / 4;
        k_agg_rel<<<(ng * 8 + 255) / 256, 256>>>(
            (const float4*)x_sw, (const int4*)src_sp, (const int4*)dst_sp,
            p_sum_sp, p_cnt_sp, (int*)nullptr, ng);
    }
    cudaEventRecord(g_res.e1, 0);

    // --- side stream: PFAS epilogue ---
    cudaStreamWaitEvent(S, g_res.e1, 0);
    k_fin_pfas<<<NB_PF, 256, 0, S>>>(x_pfas, ea_gp,
                                     Wl_gp, bl_gp, Wr_gp, We_gp, be_gp,
                                     Wl_sp, bl_sp, Wr_sp, out_pfas);

    // --- main stream: ps aggregation ---
    {
        int ng = E_PS / 4;
        k_agg_rel<<<(ng * 8 + 255) / 256, 256>>>(
            (const float4*)x_pfas, (const int4*)src_ps, (const int4*)dst_ps,
            p_sum_ps, p_cnt_ps, (int*)nullptr, ng);
    }
    cudaEventRecord(g_res.e2, 0);

    // --- side stream: SW epilogue, then join back to origin ---
    cudaStreamWaitEvent(S, g_res.e2, 0);
    k_fin_sw<<<NB_SW, 256, 0, S>>>(x_sw, Wl_ps, bl_ps, Wr_ps, out_sw);
    cudaEventRecord(g_res.e3, S);
    cudaStreamWaitEvent(0, g_res.e3, 0);

    (void)in_sizes; (void)n_in; (void)out_size;
}

// round 15
// speedup vs baseline: 1.1618x; 1.1618x over previous
#include <cuda_runtime.h>

// ---------------------------------------------------------------------------
// Problem constants
// ---------------------------------------------------------------------------
#define N_PFAS 50000
#define N_GW   200000
#define N_SW   20000
#define D      32
#define E_PG   2000000
#define E_GP   2000000
#define E_PS   1000000
#define E_SP   1000000

#define OFF_Y   (N_PFAS * D)
#define OFF_SW  (N_PFAS * D + N_GW)

#define NB_PF  ((N_PFAS + 255) / 256)   // 196
#define NB_SW  ((N_SW + 255) / 256)     // 79
#define GW_GRID 296                     // ~2 blocks/SM: caps fin_gw footprint

typedef unsigned long long u64;

// ---------------------------------------------------------------------------
// Scratch (device globals; allocation-free). 16B aligned for v4 atomics/loads.
// ---------------------------------------------------------------------------
__device__ __align__(16) float g_sum_pg[(size_t)N_GW * D];
__device__ __align__(16) float g_cnt_pg[N_GW];
__device__ __align__(16) int   g_maxe_pg[N_GW];

__device__ __align__(16) float g_sum_gp[(size_t)N_PFAS * D];
__device__ __align__(16) float g_cnt_gp[N_PFAS];
__device__ __align__(16) int   g_maxe_gp[N_PFAS];

__device__ __align__(16) float g_sum_sp[(size_t)N_PFAS * D];
__device__ __align__(16) float g_cnt_sp[N_PFAS];

__device__ __align__(16) float g_sum_ps[(size_t)N_SW * D];
__device__ __align__(16) float g_cnt_ps[N_SW];

// ---------------------------------------------------------------------------
// Static stream/events for the capture-graph fork (exact R12 set).
// ---------------------------------------------------------------------------
struct OverlapRes {
    cudaStream_t s;
    cudaEvent_t  e0, e1, e2, e3;
    OverlapRes() {
        cudaStreamCreateWithFlags(&s, cudaStreamNonBlocking);
        cudaEventCreateWithFlags(&e0, cudaEventDisableTiming);
        cudaEventCreateWithFlags(&e1, cudaEventDisableTiming);
        cudaEventCreateWithFlags(&e2, cudaEventDisableTiming);
        cudaEventCreateWithFlags(&e3, cudaEventDisableTiming);
    }
};
static OverlapRes g_res;

// ---------------------------------------------------------------------------
// Packed f32x2 helpers (sm_100+)
// ---------------------------------------------------------------------------
__device__ __forceinline__ u64 pk2(float x) {
    u64 d; unsigned xi = __float_as_uint(x);
    asm("mov.b64 %0, {%1, %1};" : "=l"(d) : "r"(xi));
    return d;
}
__device__ __forceinline__ u64 pk2f(float a, float b) {
    u64 d; unsigned ai = __float_as_uint(a), bi = __float_as_uint(b);
    asm("mov.b64 %0, {%1, %2};" : "=l"(d) : "r"(ai), "r"(bi));
    return d;
}
__device__ __forceinline__ u64 f2fma(u64 a, u64 b, u64 c) {
    u64 d; asm("fma.rn.f32x2 %0, %1, %2, %3;" : "=l"(d) : "l"(a), "l"(b), "l"(c));
    return d;
}
__device__ __forceinline__ u64 f2add(u64 a, u64 b) {
    u64 d; asm("add.rn.f32x2 %0, %1, %2;" : "=l"(d) : "l"(a), "l"(b));
    return d;
}
__device__ __forceinline__ float2 up2(u64 a) {
    unsigned lo, hi;
    asm("mov.b64 {%0, %1}, %2;" : "=r"(lo), "=r"(hi) : "l"(a));
    return make_float2(__uint_as_float(lo), __uint_as_float(hi));
}

__device__ __forceinline__ void red_add_v4(float* addr, float4 v) {
    asm volatile("red.global.add.v4.f32 [%0], {%1,%2,%3,%4};"
                 :: "l"(addr), "f"(v.x), "f"(v.y), "f"(v.z), "f"(v.w)
                 : "memory");
}

// ---------------------------------------------------------------------------
// Init: single kernel on main stream (R12 position), vectorized stores.
// ---------------------------------------------------------------------------
__global__ void k_init() {
    int i = blockIdx.x * blockDim.x + threadIdx.x;
    int stride = gridDim.x * blockDim.x;
    float4 z4 = make_float4(0.f, 0.f, 0.f, 0.f);
    int4 m4 = make_int4(-1, -1, -1, -1);

    float4* spg = (float4*)g_sum_pg;
    for (int j = i; j < N_GW * D / 4; j += stride) spg[j] = z4;
    float4* sgp = (float4*)g_sum_gp;
    float4* ssp = (float4*)g_sum_sp;
    for (int j = i; j < N_PFAS * D / 4; j += stride) { sgp[j] = z4; ssp[j] = z4; }
    float4* sps = (float4*)g_sum_ps;
    for (int j = i; j < N_SW * D / 4; j += stride) sps[j] = z4;

    float4* cpg = (float4*)g_cnt_pg;
    int4*   mpg = (int4*)g_maxe_pg;
    for (int j = i; j < N_GW / 4; j += stride) { cpg[j] = z4; mpg[j] = m4; }
    float4* cgp = (float4*)g_cnt_gp;
    float4* csp = (float4*)g_cnt_sp;
    int4*   mgp = (int4*)g_maxe_gp;
    for (int j = i; j < N_PFAS / 4; j += stride) { cgp[j] = z4; csp[j] = z4; mgp[j] = m4; }
    float4* cps = (float4*)g_cnt_ps;
    for (int j = i; j < N_SW / 4; j += stride) cps[j] = z4;
}

// ---------------------------------------------------------------------------
// Single-relation edge aggregation (8-lane groups, 4 edges/group)
// ---------------------------------------------------------------------------
__global__ void k_agg_rel(const float4* __restrict__ X,
                          const int4*   __restrict__ src4,
                          const int4*   __restrict__ dst4,
                          float* __restrict__ sum,
                          float* __restrict__ cnt,
                          int*   __restrict__ maxe,
                          int ngroups)
{
    int t   = blockIdx.x * blockDim.x + threadIdx.x;
    int g   = t >> 3;
    int seg = t & 7;
    if (g >= ngroups) return;

    int4 s4 = __ldg(&src4[g]);
    int4 d4 = __ldg(&dst4[g]);

    float4 v0 = __ldg(&X[(size_t)s4.x * 8 + seg]);
    float4 v1 = __ldg(&X[(size_t)s4.y * 8 + seg]);
    float4 v2 = __ldg(&X[(size_t)s4.z * 8 + seg]);
    float4 v3 = __ldg(&X[(size_t)s4.w * 8 + seg]);

    red_add_v4(&sum[(size_t)d4.x * D + seg * 4], v0);
    red_add_v4(&sum[(size_t)d4.y * D + seg * 4], v1);
    red_add_v4(&sum[(size_t)d4.z * D + seg * 4], v2);
    red_add_v4(&sum[(size_t)d4.w * D + seg * 4], v3);

    if (seg == 0) {
        atomicAdd(&cnt[d4.x], 1.0f);
        atomicAdd(&cnt[d4.y], 1.0f);
        atomicAdd(&cnt[d4.z], 1.0f);
        atomicAdd(&cnt[d4.w], 1.0f);
        if (maxe) {
            int e0 = g * 4;
            atomicMax(&maxe[d4.x], e0);
            atomicMax(&maxe[d4.y], e0 + 1);
            atomicMax(&maxe[d4.z], e0 + 2);
            atomicMax(&maxe[d4.w], e0 + 3);
        }
    }
}

// ---------------------------------------------------------------------------
// Thread-per-node epilogues
// ---------------------------------------------------------------------------
__device__ __forceinline__ void load_row(const float* base, size_t n, float inv, float x[32]) {
    const float4* r4 = (const float4*)(base + n * D);
#pragma unroll
    for (int q = 0; q < 8; q++) {
        float4 v = __ldg(&r4[q]);
        x[q * 4 + 0] = v.x * inv; x[q * 4 + 1] = v.y * inv;
        x[q * 4 + 2] = v.z * inv; x[q * 4 + 3] = v.w * inv;
    }
}

__device__ __forceinline__ void mv_acc(const float* sW, const float x[32], u64 acc[16]) {
#pragma unroll
    for (int k = 0; k < 32; k++) {
        u64 xk = pk2(x[k]);
        const u64* w2 = (const u64*)(sW + k * 32);
#pragma unroll
        for (int jj = 0; jj < 16; jj++) acc[jj] = f2fma(xk, w2[jj], acc[jj]);
    }
}

__device__ __forceinline__ void edge_acc(const float* __restrict__ ea, int me,
                                         const float* sWe, const float* sbe,
                                         u64 acc[16]) {
    u64 e0 = pk2(__ldg(&ea[3 * (size_t)me + 0]));
    u64 e1 = pk2(__ldg(&ea[3 * (size_t)me + 1]));
    u64 e2 = pk2(__ldg(&ea[3 * (size_t)me + 2]));
    const u64* w0 = (const u64*)(sWe);
    const u64* w1 = (const u64*)(sWe + 32);
    const u64* w2 = (const u64*)(sWe + 64);
#pragma unroll
    for (int jj = 0; jj < 16; jj++) {
        u64 a = acc[jj];
        a = f2fma(e0, w0[jj], a);
        a = f2fma(e1, w1[jj], a);
        a = f2fma(e2, w2[jj], a);
        a = f2add(a, pk2f(sbe[2 * jj], sbe[2 * jj + 1]));
        acc[jj] = a;
    }
}

// GW epilogue: grid-stride, footprint-capped at GW_GRID blocks.
__global__ void __launch_bounds__(256) k_fin_gw(
        const float* __restrict__ x_gw, const float* __restrict__ ea,
        const float* __restrict__ Wl, const float* __restrict__ bl,
        const float* __restrict__ Wr, const float* __restrict__ We,
        const float* __restrict__ be, const float* __restrict__ Wo,
        const float* __restrict__ bout, const float* __restrict__ apre,
        float* __restrict__ y)
{
    __shared__ __align__(16) float sW[2 * 1024];
    __shared__ __align__(16) float sWe[96];
    __shared__ float sb[32], sbe[32], sWo[32];
    int tid = threadIdx.x;
    for (int j = tid; j < 1024; j += 256) { sW[j] = Wl[j]; sW[1024 + j] = Wr[j]; }
    if (tid < 96) sWe[tid] = We[tid];
    if (tid < 32) { sb[tid] = bl[tid]; sbe[tid] = be[tid]; sWo[tid] = Wo[tid]; }
    __syncthreads();

    float bo = __ldg(&bout[0]);
    float a_ = __ldg(&apre[0]);

    for (int n0 = blockIdx.x * 256; n0 < N_GW; n0 += gridDim.x * 256) {
        int n = n0 + tid;
        if (n >= N_GW) continue;

        u64 acc[16];
#pragma unroll
        for (int jj = 0; jj < 16; jj++) acc[jj] = pk2f(sb[2 * jj], sb[2 * jj + 1]);

        float inv = 1.0f / fmaxf(g_cnt_pg[n], 1.0f);
        float xr[32];
        load_row(g_sum_pg, (size_t)n, inv, xr);
        mv_acc(sW, xr, acc);
        load_row(x_gw, (size_t)n, 1.0f, xr);
        mv_acc(sW + 1024, xr, acc);

        int me = g_maxe_pg[n];
        if (me >= 0) edge_acc(ea, me, sWe, sbe, acc);

        float yv = 0.0f;
#pragma unroll
        for (int jj = 0; jj < 16; jj++) {
            float2 h = up2(acc[jj]);
            yv += fmaxf(h.x, 0.0f) * sWo[2 * jj] + fmaxf(h.y, 0.0f) * sWo[2 * jj + 1];
        }
        yv += bo;
        y[n] = (yv >= 0.0f) ? yv : a_ * yv;
    }
}

__global__ void __launch_bounds__(256) k_fin_pfas(
        const float* __restrict__ x_pfas, const float* __restrict__ ea,
        const float* __restrict__ Wl_gp, const float* __restrict__ bl_gp,
        const float* __restrict__ Wr_gp, const float* __restrict__ We_gp,
        const float* __restrict__ be_gp,
        const float* __restrict__ Wl_sp, const float* __restrict__ bl_sp,
        const float* __restrict__ Wr_sp,
        float* __restrict__ h_out)
{
    __shared__ __align__(16) float sW[3 * 1024];
    __shared__ __align__(16) float sWe[96];
    __shared__ float sb[32], sbe[32];
    int tid = threadIdx.x;
    for (int j = tid; j < 1024; j += 256) {
        sW[j]        = Wl_gp[j];
        sW[1024 + j] = Wl_sp[j];
        sW[2048 + j] = Wr_gp[j] + Wr_sp[j];
    }
    if (tid < 96) sWe[tid] = We_gp[tid];
    if (tid < 32) { sb[tid] = bl_gp[tid] + bl_sp[tid]; sbe[tid] = be_gp[tid]; }
    __syncthreads();

    int n = blockIdx.x * 256 + tid;
    if (n >= N_PFAS) return;

    u64 acc[16];
#pragma unroll
    for (int jj = 0; jj < 16; jj++) acc[jj] = pk2f(sb[2 * jj], sb[2 * jj + 1]);

    float invg = 1.0f / fmaxf(g_cnt_gp[n], 1.0f);
    float invs = 1.0f / fmaxf(g_cnt_sp[n], 1.0f);
    float xr[32];
    load_row(g_sum_gp, (size_t)n, invg, xr);
    mv_acc(sW, xr, acc);
    load_row(g_sum_sp, (size_t)n, invs, xr);
    mv_acc(sW + 1024, xr, acc);
    load_row(x_pfas, (size_t)n, 1.0f, xr);
    mv_acc(sW + 2048, xr, acc);

    int me = g_maxe_gp[n];
    if (me >= 0) edge_acc(ea, me, sWe, sbe, acc);

    float4* o4 = (float4*)(h_out + (size_t)n * D);
#pragma unroll
    for (int q = 0; q < 8; q++) {
        float2 a = up2(acc[2 * q]);
        float2 c = up2(acc[2 * q + 1]);
        o4[q] = make_float4(fmaxf(a.x, 0.f), fmaxf(a.y, 0.f),
                            fmaxf(c.x, 0.f), fmaxf(c.y, 0.f));
    }
}

__global__ void __launch_bounds__(256) k_fin_sw(
        const float* __restrict__ x_sw,
        const float* __restrict__ Wl, const float* __restrict__ bl,
        const float* __restrict__ Wr,
        float* __restrict__ h_out)
{
    __shared__ __align__(16) float sW[2 * 1024];
    __shared__ float sb[32];
    int tid = threadIdx.x;
    for (int j = tid; j < 1024; j += 256) { sW[j] = Wl[j]; sW[1024 + j] = Wr[j]; }
    if (tid < 32) sb[tid] = bl[tid];
    __syncthreads();

    int n = blockIdx.x * 256 + tid;
    if (n >= N_SW) return;

    u64 acc[16];
#pragma unroll
    for (int jj = 0; jj < 16; jj++) acc[jj] = pk2f(sb[2 * jj], sb[2 * jj + 1]);

    float inv = 1.0f / fmaxf(g_cnt_ps[n], 1.0f);
    float xr[32];
    load_row(g_sum_ps, (size_t)n, inv, xr);
    mv_acc(sW, xr, acc);
    load_row(x_sw, (size_t)n, 1.0f, xr);
    mv_acc(sW + 1024, xr, acc);

    float4* o4 = (float4*)(h_out + (size_t)n * D);
#pragma unroll
    for (int q = 0; q < 8; q++) {
        float2 a = up2(acc[2 * q]);
        float2 c = up2(acc[2 * q + 1]);
        o4[q] = make_float4(fmaxf(a.x, 0.f), fmaxf(a.y, 0.f),
                            fmaxf(c.x, 0.f), fmaxf(c.y, 0.f));
    }
}

// ---------------------------------------------------------------------------
// Launch: EXACT R12 forked schedule.
//   main : init -> agg_pg -> [E0] -> agg_gp -> agg_sp -> [E1] -> agg_ps
//          -> [E2] -> wait(E3)
//   side : wait(E0) -> fin_gw -> wait(E1) -> fin_pfas -> wait(E2) -> fin_sw
//          -> [E3]
// ---------------------------------------------------------------------------
extern "C" void kernel_launch(void* const* d_in, const int* in_sizes, int n_in,
                              void* d_out, int out_size)
{
    const float* x_pfas = (const float*)d_in[0];
    const float* x_gw   = (const float*)d_in[1];
    const float* x_sw   = (const float*)d_in[2];
    const int*   src_pg = (const int*)d_in[3];
    const int*   dst_pg = (const int*)d_in[4];
    const float* ea_pg  = (const float*)d_in[5];
    const int*   src_gp = (const int*)d_in[6];
    const int*   dst_gp = (const int*)d_in[7];
    const float* ea_gp  = (const float*)d_in[8];
    const int*   src_ps = (const int*)d_in[9];
    const int*   dst_ps = (const int*)d_in[10];
    const int*   src_sp = (const int*)d_in[11];
    const int*   dst_sp = (const int*)d_in[12];
    const float* Wl_pg  = (const float*)d_in[13];
    const float* bl_pg  = (const float*)d_in[14];
    const float* Wr_pg  = (const float*)d_in[15];
    const float* We_pg  = (const float*)d_in[16];
    const float* be_pg  = (const float*)d_in[17];
    const float* Wl_gp  = (const float*)d_in[18];
    const float* bl_gp  = (const float*)d_in[19];
    const float* Wr_gp  = (const float*)d_in[20];
    const float* We_gp  = (const float*)d_in[21];
    const float* be_gp  = (const float*)d_in[22];
    const float* Wl_ps  = (const float*)d_in[23];
    const float* bl_ps  = (const float*)d_in[24];
    const float* Wr_ps  = (const float*)d_in[25];
    const float* Wl_sp  = (const float*)d_in[26];
    const float* bl_sp  = (const float*)d_in[27];
    const float* Wr_sp  = (const float*)d_in[28];
    const float* W_out  = (const float*)d_in[29];
    const float* b_out  = (const float*)d_in[30];
    const float* a_pre  = (const float*)d_in[31];

    float* out      = (float*)d_out;
    float* out_pfas = out;
    float* out_y    = out + OFF_Y;
    float* out_sw   = out + OFF_SW;

    float *p_sum_pg, *p_cnt_pg, *p_sum_gp, *p_cnt_gp, *p_sum_sp, *p_cnt_sp, *p_sum_ps, *p_cnt_ps;
    int *p_maxe_pg, *p_maxe_gp;
    cudaGetSymbolAddress((void**)&p_sum_pg, g_sum_pg);
    cudaGetSymbolAddress((void**)&p_cnt_pg, g_cnt_pg);
    cudaGetSymbolAddress((void**)&p_sum_gp, g_sum_gp);
    cudaGetSymbolAddress((void**)&p_cnt_gp, g_cnt_gp);
    cudaGetSymbolAddress((void**)&p_sum_sp, g_sum_sp);
    cudaGetSymbolAddress((void**)&p_cnt_sp, g_cnt_sp);
    cudaGetSymbolAddress((void**)&p_sum_ps, g_sum_ps);
    cudaGetSymbolAddress((void**)&p_cnt_ps, g_cnt_ps);
    cudaGetSymbolAddress((void**)&p_maxe_pg, g_maxe_pg);
    cudaGetSymbolAddress((void**)&p_maxe_gp, g_maxe_gp);

    cudaStream_t S = g_res.s;

    // --- main stream: init (vectorized) + pg aggregation ---
    k_init<<<2048, 256>>>();
    {
        int ng = E_PG / 4;
        k_agg_rel<<<(ng * 8 + 255) / 256, 256>>>(
            (const float4*)x_pfas, (const int4*)src_pg, (const int4*)dst_pg,
            p_sum_pg, p_cnt_pg, p_maxe_pg, ng);
    }
    cudaEventRecord(g_res.e0, 0);

    // --- side stream: GW epilogue (footprint-capped) overlaps remaining aggs ---
    cudaStreamWaitEvent(S, g_res.e0, 0);
    k_fin_gw<<<GW_GRID, 256, 0, S>>>(x_gw, ea_pg,
                                     Wl_pg, bl_pg, Wr_pg, We_pg, be_pg,
                                     W_out, b_out, a_pre, out_y);

    // --- main stream: gp + sp aggregations ---
    {
        int ng = E_GP / 4;
        k_agg_rel<<<(ng * 8 + 255) / 256, 256>>>(
            (const float4*)x_gw, (const int4*)src_gp, (const int4*)dst_gp,
            p_sum_gp, p_cnt_gp, p_maxe_gp, ng);
    }
    {
        int ng = E_SP / 4;
        k_agg_rel<<<(ng * 8 + 255) / 256, 256>>>(
            (const float4*)x_sw, (const int4*)src_sp, (const int4*)dst_sp,
            p_sum_sp, p_cnt_sp, (int*)nullptr, ng);
    }
    cudaEventRecord(g_res.e1, 0);

    // --- side stream: PFAS epilogue ---
    cudaStreamWaitEvent(S, g_res.e1, 0);
    k_fin_pfas<<<NB_PF, 256, 0, S>>>(x_pfas, ea_gp,
                                     Wl_gp, bl_gp, Wr_gp, We_gp, be_gp,
                                     Wl_sp, bl_sp, Wr_sp, out_pfas);

    // --- main stream: ps aggregation ---
    {
        int ng = E_PS / 4;
        k_agg_rel<<<(ng * 8 + 255) / 256, 256>>>(
            (const float4*)x_pfas, (const int4*)src_ps, (const int4*)dst_ps,
            p_sum_ps, p_cnt_ps, (int*)nullptr, ng);
    }
    cudaEventRecord(g_res.e2, 0);

    // --- side stream: SW epilogue, then join back to origin ---
    cudaStreamWaitEvent(S, g_res.e2, 0);
    k_fin_sw<<<NB_SW, 256, 0, S>>>(x_sw, Wl_ps, bl_ps, Wr_ps, out_sw);
    cudaEventRecord(g_res.e3, S);
    cudaStreamWaitEvent(0, g_res.e3, 0);

    (void)in_sizes; (void)n_in; (void)out_size;
}

// round 16
// speedup vs baseline: 1.1785x; 1.0143x over previous
#include <cuda_runtime.h>

// ---------------------------------------------------------------------------
// Problem constants
// ---------------------------------------------------------------------------
#define N_PFAS 50000
#define N_GW   200000
#define N_SW   20000
#define D      32
#define E_PG   2000000
#define E_GP   2000000
#define E_PS   1000000
#define E_SP   1000000

#define OFF_Y   (N_PFAS * D)
#define OFF_SW  (N_PFAS * D + N_GW)

#define NB_PF  ((N_PFAS + 255) / 256)   // 196
#define NB_SW  ((N_SW + 255) / 256)     // 79
#define GW_GRID 222                     // ~1.5 blocks/SM: smaller fin_gw footprint

typedef unsigned long long u64;

// ---------------------------------------------------------------------------
// Scratch (device globals; allocation-free). 16B aligned for v4 atomics/loads.
// ---------------------------------------------------------------------------
__device__ __align__(16) float g_sum_pg[(size_t)N_GW * D];
__device__ __align__(16) float g_cnt_pg[N_GW];
__device__ __align__(16) int   g_maxe_pg[N_GW];

__device__ __align__(16) float g_sum_gp[(size_t)N_PFAS * D];
__device__ __align__(16) float g_cnt_gp[N_PFAS];
__device__ __align__(16) int   g_maxe_gp[N_PFAS];

__device__ __align__(16) float g_sum_sp[(size_t)N_PFAS * D];
__device__ __align__(16) float g_cnt_sp[N_PFAS];

__device__ __align__(16) float g_sum_ps[(size_t)N_SW * D];
__device__ __align__(16) float g_cnt_ps[N_SW];

// ---------------------------------------------------------------------------
// Static stream/events for the capture-graph fork (exact R12/R15 set).
// ---------------------------------------------------------------------------
struct OverlapRes {
    cudaStream_t s;
    cudaEvent_t  e0, e1, e2, e3;
    OverlapRes() {
        cudaStreamCreateWithFlags(&s, cudaStreamNonBlocking);
        cudaEventCreateWithFlags(&e0, cudaEventDisableTiming);
        cudaEventCreateWithFlags(&e1, cudaEventDisableTiming);
        cudaEventCreateWithFlags(&e2, cudaEventDisableTiming);
        cudaEventCreateWithFlags(&e3, cudaEventDisableTiming);
    }
};
static OverlapRes g_res;

// ---------------------------------------------------------------------------
// Packed f32x2 helpers (sm_100+)
// ---------------------------------------------------------------------------
__device__ __forceinline__ u64 pk2(float x) {
    u64 d; unsigned xi = __float_as_uint(x);
    asm("mov.b64 %0, {%1, %1};" : "=l"(d) : "r"(xi));
    return d;
}
__device__ __forceinline__ u64 pk2f(float a, float b) {
    u64 d; unsigned ai = __float_as_uint(a), bi = __float_as_uint(b);
    asm("mov.b64 %0, {%1, %2};" : "=l"(d) : "r"(ai), "r"(bi));
    return d;
}
__device__ __forceinline__ u64 f2fma(u64 a, u64 b, u64 c) {
    u64 d; asm("fma.rn.f32x2 %0, %1, %2, %3;" : "=l"(d) : "l"(a), "l"(b), "l"(c));
    return d;
}
__device__ __forceinline__ u64 f2add(u64 a, u64 b) {
    u64 d; asm("add.rn.f32x2 %0, %1, %2;" : "=l"(d) : "l"(a), "l"(b));
    return d;
}
__device__ __forceinline__ float2 up2(u64 a) {
    unsigned lo, hi;
    asm("mov.b64 {%0, %1}, %2;" : "=r"(lo), "=r"(hi) : "l"(a));
    return make_float2(__uint_as_float(lo), __uint_as_float(hi));
}

__device__ __forceinline__ void red_add_v4(float* addr, float4 v) {
    asm volatile("red.global.add.v4.f32 [%0], {%1,%2,%3,%4};"
                 :: "l"(addr), "f"(v.x), "f"(v.y), "f"(v.z), "f"(v.w)
                 : "memory");
}

// ---------------------------------------------------------------------------
// Init: single kernel on main stream, vectorized stores (R15).
// ---------------------------------------------------------------------------
__global__ void k_init() {
    int i = blockIdx.x * blockDim.x + threadIdx.x;
    int stride = gridDim.x * blockDim.x;
    float4 z4 = make_float4(0.f, 0.f, 0.f, 0.f);
    int4 m4 = make_int4(-1, -1, -1, -1);

    float4* spg = (float4*)g_sum_pg;
    for (int j = i; j < N_GW * D / 4; j += stride) spg[j] = z4;
    float4* sgp = (float4*)g_sum_gp;
    float4* ssp = (float4*)g_sum_sp;
    for (int j = i; j < N_PFAS * D / 4; j += stride) { sgp[j] = z4; ssp[j] = z4; }
    float4* sps = (float4*)g_sum_ps;
    for (int j = i; j < N_SW * D / 4; j += stride) sps[j] = z4;

    float4* cpg = (float4*)g_cnt_pg;
    int4*   mpg = (int4*)g_maxe_pg;
    for (int j = i; j < N_GW / 4; j += stride) { cpg[j] = z4; mpg[j] = m4; }
    float4* cgp = (float4*)g_cnt_gp;
    float4* csp = (float4*)g_cnt_sp;
    int4*   mgp = (int4*)g_maxe_gp;
    for (int j = i; j < N_PFAS / 4; j += stride) { cgp[j] = z4; csp[j] = z4; mgp[j] = m4; }
    float4* cps = (float4*)g_cnt_ps;
    for (int j = i; j < N_SW / 4; j += stride) cps[j] = z4;
}

// ---------------------------------------------------------------------------
// Single-relation edge aggregation (8-lane groups, 4 edges/group)
// ---------------------------------------------------------------------------
__global__ void k_agg_rel(const float4* __restrict__ X,
                          const int4*   __restrict__ src4,
                          const int4*   __restrict__ dst4,
                          float* __restrict__ sum,
                          float* __restrict__ cnt,
                          int*   __restrict__ maxe,
                          int ngroups)
{
    int t   = blockIdx.x * blockDim.x + threadIdx.x;
    int g   = t >> 3;
    int seg = t & 7;
    if (g >= ngroups) return;

    int4 s4 = __ldg(&src4[g]);
    int4 d4 = __ldg(&dst4[g]);

    float4 v0 = __ldg(&X[(size_t)s4.x * 8 + seg]);
    float4 v1 = __ldg(&X[(size_t)s4.y * 8 + seg]);
    float4 v2 = __ldg(&X[(size_t)s4.z * 8 + seg]);
    float4 v3 = __ldg(&X[(size_t)s4.w * 8 + seg]);

    red_add_v4(&sum[(size_t)d4.x * D + seg * 4], v0);
    red_add_v4(&sum[(size_t)d4.y * D + seg * 4], v1);
    red_add_v4(&sum[(size_t)d4.z * D + seg * 4], v2);
    red_add_v4(&sum[(size_t)d4.w * D + seg * 4], v3);

    if (seg == 0) {
        atomicAdd(&cnt[d4.x], 1.0f);
        atomicAdd(&cnt[d4.y], 1.0f);
        atomicAdd(&cnt[d4.z], 1.0f);
        atomicAdd(&cnt[d4.w], 1.0f);
        if (maxe) {
            int e0 = g * 4;
            atomicMax(&maxe[d4.x], e0);
            atomicMax(&maxe[d4.y], e0 + 1);
            atomicMax(&maxe[d4.z], e0 + 2);
            atomicMax(&maxe[d4.w], e0 + 3);
        }
    }
}

// ---------------------------------------------------------------------------
// Thread-per-node epilogues
// ---------------------------------------------------------------------------
__device__ __forceinline__ void load_row(const float* base, size_t n, float inv, float x[32]) {
    const float4* r4 = (const float4*)(base + n * D);
#pragma unroll
    for (int q = 0; q < 8; q++) {
        float4 v = __ldg(&r4[q]);
        x[q * 4 + 0] = v.x * inv; x[q * 4 + 1] = v.y * inv;
        x[q * 4 + 2] = v.z * inv; x[q * 4 + 3] = v.w * inv;
    }
}

__device__ __forceinline__ void mv_acc(const float* sW, const float x[32], u64 acc[16]) {
#pragma unroll
    for (int k = 0; k < 32; k++) {
        u64 xk = pk2(x[k]);
        const u64* w2 = (const u64*)(sW + k * 32);
#pragma unroll
        for (int jj = 0; jj < 16; jj++) acc[jj] = f2fma(xk, w2[jj], acc[jj]);
    }
}

__device__ __forceinline__ void edge_acc(const float* __restrict__ ea, int me,
                                         const float* sWe, const float* sbe,
                                         u64 acc[16]) {
    u64 e0 = pk2(__ldg(&ea[3 * (size_t)me + 0]));
    u64 e1 = pk2(__ldg(&ea[3 * (size_t)me + 1]));
    u64 e2 = pk2(__ldg(&ea[3 * (size_t)me + 2]));
    const u64* w0 = (const u64*)(sWe);
    const u64* w1 = (const u64*)(sWe + 32);
    const u64* w2 = (const u64*)(sWe + 64);
#pragma unroll
    for (int jj = 0; jj < 16; jj++) {
        u64 a = acc[jj];
        a = f2fma(e0, w0[jj], a);
        a = f2fma(e1, w1[jj], a);
        a = f2fma(e2, w2[jj], a);
        a = f2add(a, pk2f(sbe[2 * jj], sbe[2 * jj + 1]));
        acc[jj] = a;
    }
}

// GW epilogue: grid-stride, footprint-capped at GW_GRID blocks.
__global__ void __launch_bounds__(256) k_fin_gw(
        const float* __restrict__ x_gw, const float* __restrict__ ea,
        const float* __restrict__ Wl, const float* __restrict__ bl,
        const float* __restrict__ Wr, const float* __restrict__ We,
        const float* __restrict__ be, const float* __restrict__ Wo,
        const float* __restrict__ bout, const float* __restrict__ apre,
        float* __restrict__ y)
{
    __shared__ __align__(16) float sW[2 * 1024];
    __shared__ __align__(16) float sWe[96];
    __shared__ float sb[32], sbe[32], sWo[32];
    int tid = threadIdx.x;
    for (int j = tid; j < 1024; j += 256) { sW[j] = Wl[j]; sW[1024 + j] = Wr[j]; }
    if (tid < 96) sWe[tid] = We[tid];
    if (tid < 32) { sb[tid] = bl[tid]; sbe[tid] = be[tid]; sWo[tid] = Wo[tid]; }
    __syncthreads();

    float bo = __ldg(&bout[0]);
    float a_ = __ldg(&apre[0]);

    for (int n0 = blockIdx.x * 256; n0 < N_GW; n0 += gridDim.x * 256) {
        int n = n0 + tid;
        if (n >= N_GW) continue;

        u64 acc[16];
#pragma unroll
        for (int jj = 0; jj < 16; jj++) acc[jj] = pk2f(sb[2 * jj], sb[2 * jj + 1]);

        float inv = 1.0f / fmaxf(g_cnt_pg[n], 1.0f);
        float xr[32];
        load_row(g_sum_pg, (size_t)n, inv, xr);
        mv_acc(sW, xr, acc);
        load_row(x_gw, (size_t)n, 1.0f, xr);
        mv_acc(sW + 1024, xr, acc);

        int me = g_maxe_pg[n];
        if (me >= 0) edge_acc(ea, me, sWe, sbe, acc);

        float yv = 0.0f;
#pragma unroll
        for (int jj = 0; jj < 16; jj++) {
            float2 h = up2(acc[jj]);
            yv += fmaxf(h.x, 0.0f) * sWo[2 * jj] + fmaxf(h.y, 0.0f) * sWo[2 * jj + 1];
        }
        yv += bo;
        y[n] = (yv >= 0.0f) ? yv : a_ * yv;
    }
}

__global__ void __launch_bounds__(256) k_fin_pfas(
        const float* __restrict__ x_pfas, const float* __restrict__ ea,
        const float* __restrict__ Wl_gp, const float* __restrict__ bl_gp,
        const float* __restrict__ Wr_gp, const float* __restrict__ We_gp,
        const float* __restrict__ be_gp,
        const float* __restrict__ Wl_sp, const float* __restrict__ bl_sp,
        const float* __restrict__ Wr_sp,
        float* __restrict__ h_out)
{
    __shared__ __align__(16) float sW[3 * 1024];
    __shared__ __align__(16) float sWe[96];
    __shared__ float sb[32], sbe[32];
    int tid = threadIdx.x;
    for (int j = tid; j < 1024; j += 256) {
        sW[j]        = Wl_gp[j];
        sW[1024 + j] = Wl_sp[j];
        sW[2048 + j] = Wr_gp[j] + Wr_sp[j];
    }
    if (tid < 96) sWe[tid] = We_gp[tid];
    if (tid < 32) { sb[tid] = bl_gp[tid] + bl_sp[tid]; sbe[tid] = be_gp[tid]; }
    __syncthreads();

    int n = blockIdx.x * 256 + tid;
    if (n >= N_PFAS) return;

    u64 acc[16];
#pragma unroll
    for (int jj = 0; jj < 16; jj++) acc[jj] = pk2f(sb[2 * jj], sb[2 * jj + 1]);

    float invg = 1.0f / fmaxf(g_cnt_gp[n], 1.0f);
    float invs = 1.0f / fmaxf(g_cnt_sp[n], 1.0f);
    float xr[32];
    load_row(g_sum_gp, (size_t)n, invg, xr);
    mv_acc(sW, xr, acc);
    load_row(g_sum_sp, (size_t)n, invs, xr);
    mv_acc(sW + 1024, xr, acc);
    load_row(x_pfas, (size_t)n, 1.0f, xr);
    mv_acc(sW + 2048, xr, acc);

    int me = g_maxe_gp[n];
    if (me >= 0) edge_acc(ea, me, sWe, sbe, acc);

    float4* o4 = (float4*)(h_out + (size_t)n * D);
#pragma unroll
    for (int q = 0; q < 8; q++) {
        float2 a = up2(acc[2 * q]);
        float2 c = up2(acc[2 * q + 1]);
        o4[q] = make_float4(fmaxf(a.x, 0.f), fmaxf(a.y, 0.f),
                            fmaxf(c.x, 0.f), fmaxf(c.y, 0.f));
    }
}

__global__ void __launch_bounds__(256) k_fin_sw(
        const float* __restrict__ x_sw,
        const float* __restrict__ Wl, const float* __restrict__ bl,
        const float* __restrict__ Wr,
        float* __restrict__ h_out)
{
    __shared__ __align__(16) float sW[2 * 1024];
    __shared__ float sb[32];
    int tid = threadIdx.x;
    for (int j = tid; j < 1024; j += 256) { sW[j] = Wl[j]; sW[1024 + j] = Wr[j]; }
    if (tid < 32) sb[tid] = bl[tid];
    __syncthreads();

    int n = blockIdx.x * 256 + tid;
    if (n >= N_SW) return;

    u64 acc[16];
#pragma unroll
    for (int jj = 0; jj < 16; jj++) acc[jj] = pk2f(sb[2 * jj], sb[2 * jj + 1]);

    float inv = 1.0f / fmaxf(g_cnt_ps[n], 1.0f);
    float xr[32];
    load_row(g_sum_ps, (size_t)n, inv, xr);
    mv_acc(sW, xr, acc);
    load_row(x_sw, (size_t)n, 1.0f, xr);
    mv_acc(sW + 1024, xr, acc);

    float4* o4 = (float4*)(h_out + (size_t)n * D);
#pragma unroll
    for (int q = 0; q < 8; q++) {
        float2 a = up2(acc[2 * q]);
        float2 c = up2(acc[2 * q + 1]);
        o4[q] = make_float4(fmaxf(a.x, 0.f), fmaxf(a.y, 0.f),
                            fmaxf(c.x, 0.f), fmaxf(c.y, 0.f));
    }
}

// ---------------------------------------------------------------------------
// Launch: EXACT R12/R15 forked schedule.
//   main : init -> agg_pg -> [E0] -> agg_gp -> agg_sp -> [E1] -> agg_ps
//          -> [E2] -> wait(E3)
//   side : wait(E0) -> fin_gw -> wait(E1) -> fin_pfas -> wait(E2) -> fin_sw
//          -> [E3]
// ---------------------------------------------------------------------------
extern "C" void kernel_launch(void* const* d_in, const int* in_sizes, int n_in,
                              void* d_out, int out_size)
{
    const float* x_pfas = (const float*)d_in[0];
    const float* x_gw   = (const float*)d_in[1];
    const float* x_sw   = (const float*)d_in[2];
    const int*   src_pg = (const int*)d_in[3];
    const int*   dst_pg = (const int*)d_in[4];
    const float* ea_pg  = (const float*)d_in[5];
    const int*   src_gp = (const int*)d_in[6];
    const int*   dst_gp = (const int*)d_in[7];
    const float* ea_gp  = (const float*)d_in[8];
    const int*   src_ps = (const int*)d_in[9];
    const int*   dst_ps = (const int*)d_in[10];
    const int*   src_sp = (const int*)d_in[11];
    const int*   dst_sp = (const int*)d_in[12];
    const float* Wl_pg  = (const float*)d_in[13];
    const float* bl_pg  = (const float*)d_in[14];
    const float* Wr_pg  = (const float*)d_in[15];
    const float* We_pg  = (const float*)d_in[16];
    const float* be_pg  = (const float*)d_in[17];
    const float* Wl_gp  = (const float*)d_in[18];
    const float* bl_gp  = (const float*)d_in[19];
    const float* Wr_gp  = (const float*)d_in[20];
    const float* We_gp  = (const float*)d_in[21];
    const float* be_gp  = (const float*)d_in[22];
    const float* Wl_ps  = (const float*)d_in[23];
    const float* bl_ps  = (const float*)d_in[24];
    const float* Wr_ps  = (const float*)d_in[25];
    const float* Wl_sp  = (const float*)d_in[26];
    const float* bl_sp  = (const float*)d_in[27];
    const float* Wr_sp  = (const float*)d_in[28];
    const float* W_out  = (const float*)d_in[29];
    const float* b_out  = (const float*)d_in[30];
    const float* a_pre  = (const float*)d_in[31];

    float* out      = (float*)d_out;
    float* out_pfas = out;
    float* out_y    = out + OFF_Y;
    float* out_sw   = out + OFF_SW;

    float *p_sum_pg, *p_cnt_pg, *p_sum_gp, *p_cnt_gp, *p_sum_sp, *p_cnt_sp, *p_sum_ps, *p_cnt_ps;
    int *p_maxe_pg, *p_maxe_gp;
    cudaGetSymbolAddress((void**)&p_sum_pg, g_sum_pg);
    cudaGetSymbolAddress((void**)&p_cnt_pg, g_cnt_pg);
    cudaGetSymbolAddress((void**)&p_sum_gp, g_sum_gp);
    cudaGetSymbolAddress((void**)&p_cnt_gp, g_cnt_gp);
    cudaGetSymbolAddress((void**)&p_sum_sp, g_sum_sp);
    cudaGetSymbolAddress((void**)&p_cnt_sp, g_cnt_sp);
    cudaGetSymbolAddress((void**)&p_sum_ps, g_sum_ps);
    cudaGetSymbolAddress((void**)&p_cnt_ps, g_cnt_ps);
    cudaGetSymbolAddress((void**)&p_maxe_pg, g_maxe_pg);
    cudaGetSymbolAddress((void**)&p_maxe_gp, g_maxe_gp);

    cudaStream_t S = g_res.s;

    // --- main stream: init (vectorized) + pg aggregation ---
    k_init<<<2048, 256>>>();
    {
        int ng = E_PG / 4;
        k_agg_rel<<<(ng * 8 + 255) / 256, 256>>>(
            (const float4*)x_pfas, (const int4*)src_pg, (const int4*)dst_pg,
            p_sum_pg, p_cnt_pg, p_maxe_pg, ng);
    }
    cudaEventRecord(g_res.e0, 0);

    // --- side stream: GW epilogue (footprint-capped) overlaps remaining aggs ---
    cudaStreamWaitEvent(S, g_res.e0, 0);
    k_fin_gw<<<GW_GRID, 256, 0, S>>>(x_gw, ea_pg,
                                     Wl_pg, bl_pg, Wr_pg, We_pg, be_pg,
                                     W_out, b_out, a_pre, out_y);

    // --- main stream: gp + sp aggregations ---
    {
        int ng = E_GP / 4;
        k_agg_rel<<<(ng * 8 + 255) / 256, 256>>>(
            (const float4*)x_gw, (const int4*)src_gp, (const int4*)dst_gp,
            p_sum_gp, p_cnt_gp, p_maxe_gp, ng);
    }
    {
        int ng = E_SP / 4;
        k_agg_rel<<<(ng * 8 + 255) / 256, 256>>>(
            (const float4*)x_sw, (const int4*)src_sp, (const int4*)dst_sp,
            p_sum_sp, p_cnt_sp, (int*)nullptr, ng);
    }
    cudaEventRecord(g_res.e1, 0);

    // --- side stream: PFAS epilogue ---
    cudaStreamWaitEvent(S, g_res.e1, 0);
    k_fin_pfas<<<NB_PF, 256, 0, S>>>(x_pfas, ea_gp,
                                     Wl_gp, bl_gp, Wr_gp, We_gp, be_gp,
                                     Wl_sp, bl_sp, Wr_sp, out_pfas);

    // --- main stream: ps aggregation ---
    {
        int ng = E_PS / 4;
        k_agg_rel<<<(ng * 8 + 255) / 256, 256>>>(
            (const float4*)x_pfas, (const int4*)src_ps, (const int4*)dst_ps,
            p_sum_ps, p_cnt_ps, (int*)nullptr, ng);
    }
    cudaEventRecord(g_res.e2, 0);

    // --- side stream: SW epilogue, then join back to origin ---
    cudaStreamWaitEvent(S, g_res.e2, 0);
    k_fin_sw<<<NB_SW, 256, 0, S>>>(x_sw, Wl_ps, bl_ps, Wr_ps, out_sw);
    cudaEventRecord(g_res.e3, S);
    cudaStreamWaitEvent(0, g_res.e3, 0);

    (void)in_sizes; (void)n_in; (void)out_size;
}